// round 4
// baseline (speedup 1.0000x reference)
#include <cuda_runtime.h>
#include <cuda_bf16.h>
#include <math.h>
#include <stdint.h>

// ---------------- problem constants ----------------
#define BB   8
#define NN   20000
#define FEAT 256
#define HD   512
#define CATK 4096      // BB*HD
#define F1   1024
#define NCHUNK 313     // ceil(20000/64)

// ---------------- scratch ----------------
__device__ float          d_hf[BB * NN * HD];
__device__ __nv_bfloat16  d_h1hi[BB * NN * HD];
__device__ __nv_bfloat16  d_h1lo[BB * NN * HD];
__device__ __nv_bfloat16  d_h2hi[BB * NN * HD];
__device__ __nv_bfloat16  d_h2lo[BB * NN * HD];
__device__ __nv_bfloat16  d_xhi[BB * NN * FEAT];
__device__ __nv_bfloat16  d_xlo[BB * NN * FEAT];
__device__ __nv_bfloat16  d_w1hi[BB * HD * FEAT];
__device__ __nv_bfloat16  d_w1lo[BB * HD * FEAT];
__device__ __nv_bfloat16  d_w2hi[BB * HD * HD];
__device__ __nv_bfloat16  d_w2lo[BB * HD * HD];
__device__ __nv_bfloat16  d_wfhi[F1 * CATK];
__device__ __nv_bfloat16  d_wflo[F1 * CATK];
__device__ float d_f [NN * F1];
__device__ float d_f2[NN * 32];
__device__ float d_ps[BB * NCHUNK * HD];
__device__ float d_pq[BB * NCHUNK * HD];
__device__ float d_scale[BB * HD];
__device__ float d_shift[BB * HD];
__device__ float d_wall[F1 * 9 * 32];

// ---------------- helpers ----------------
__device__ __forceinline__ void splitf(float v, __nv_bfloat16& h, __nv_bfloat16& l) {
    h = __float2bfloat16(v);
    l = __float2bfloat16(v - __bfloat162float(h));
}

__device__ __forceinline__ void cpa16s(uint32_t saddr, const void* g) {
    asm volatile("cp.async.cg.shared.global [%0], [%1], 16;" :: "r"(saddr), "l"(g));
}
__device__ __forceinline__ void cpasync_commit() {
    asm volatile("cp.async.commit_group;" ::: "memory");
}
__device__ __forceinline__ void cpasync_wait1() {
    asm volatile("cp.async.wait_group 1;" ::: "memory");
}

__device__ __forceinline__ void ldsm4(uint32_t (&r)[4], uint32_t addr) {
    asm volatile("ldmatrix.sync.aligned.m8n8.x4.shared.b16 {%0,%1,%2,%3}, [%4];"
                 : "=r"(r[0]), "=r"(r[1]), "=r"(r[2]), "=r"(r[3]) : "r"(addr));
}

__device__ __forceinline__ void mma_bf16(float (&c)[4], const uint32_t (&a)[4],
                                         uint32_t b0, uint32_t b1) {
    asm volatile(
        "mma.sync.aligned.m16n8k16.row.col.f32.bf16.bf16.f32 "
        "{%0,%1,%2,%3}, {%4,%5,%6,%7}, {%8,%9}, {%0,%1,%2,%3};\n"
        : "+f"(c[0]), "+f"(c[1]), "+f"(c[2]), "+f"(c[3])
        : "r"(a[0]), "r"(a[1]), "r"(a[2]), "r"(a[3]), "r"(b0), "r"(b1));
}

// =================================================================
// split / transpose-split prep
// =================================================================
__global__ __launch_bounds__(256) void split_kernel(
    const float* __restrict__ src, __nv_bfloat16* __restrict__ hi,
    __nv_bfloat16* __restrict__ lo)
{
    size_t i = ((size_t)blockIdx.x * 256 + threadIdx.x) * 4;
    float4 v = *(const float4*)(src + i);
    __nv_bfloat16 h0, h1, h2, h3, l0, l1, l2, l3;
    splitf(v.x, h0, l0); splitf(v.y, h1, l1);
    splitf(v.z, h2, l2); splitf(v.w, h3, l3);
    __nv_bfloat162* ph = (__nv_bfloat162*)(hi + i);
    __nv_bfloat162* pl = (__nv_bfloat162*)(lo + i);
    ph[0] = __nv_bfloat162(h0, h1); ph[1] = __nv_bfloat162(h2, h3);
    pl[0] = __nv_bfloat162(l0, l1); pl[1] = __nv_bfloat162(l2, l3);
}

__global__ __launch_bounds__(256) void tsplit_kernel(
    const float* __restrict__ W, __nv_bfloat16* __restrict__ Thi,
    __nv_bfloat16* __restrict__ Tlo, int K, int N)
{
    __shared__ float t[32][33];
    int b = blockIdx.z;
    W   += (size_t)b * K * N;
    Thi += (size_t)b * N * K;
    Tlo += (size_t)b * N * K;
    int n0 = blockIdx.x * 32, k0 = blockIdx.y * 32;
    int tx = threadIdx.x & 31, ty = threadIdx.x >> 5;
#pragma unroll
    for (int i = 0; i < 4; i++)
        t[ty + i * 8][tx] = W[(size_t)(k0 + ty + i * 8) * N + n0 + tx];
    __syncthreads();
#pragma unroll
    for (int i = 0; i < 4; i++) {
        float v = t[tx][ty + i * 8];
        __nv_bfloat16 h, l;
        splitf(v, h, l);
        size_t o = (size_t)(n0 + ty + i * 8) * K + k0 + tx;
        Thi[o] = h;
        Tlo[o] = l;
    }
}

// =================================================================
// Pipelined HMMA bf16-split GEMM, 128x128x32 tiles, 3-stage cp.async,
// SW128-swizzled [128][64] smem rows (hi cols 0-31 | lo cols 32-63),
// conflict-free ldmatrix.x4 fragment loads.
// =================================================================
#define STG_A 16384           // bytes per A stage (128*64*2)
#define SB_OFF 49152          // B tiles start after 3 A stages

template<bool CAT, bool RELU>
__global__ __launch_bounds__(256, 2) void mma_gemm(
    const __nv_bfloat16* __restrict__ Ahi, const __nv_bfloat16* __restrict__ Alo,
    const __nv_bfloat16* __restrict__ Bhi, const __nv_bfloat16* __restrict__ Blo,
    const float* __restrict__ bias, float* __restrict__ C,
    int M, int N, int K)
{
    extern __shared__ __align__(16) char smem_raw[];
    const uint32_t smemBase = (uint32_t)__cvta_generic_to_shared(smem_raw);

    int b = blockIdx.z;
    if (!CAT) {
        Ahi += (size_t)b * M * K;
        Alo += (size_t)b * M * K;
    }
    Bhi  += (size_t)b * N * K;
    Blo  += (size_t)b * N * K;
    bias += (size_t)b * N;
    C    += (size_t)b * M * N;

    const int tid = threadIdx.x;
    const int m0  = blockIdx.y * 128, n0 = blockIdx.x * 128;
    const int wid = tid >> 5, lane = tid & 31;
    const int wm = (wid >> 2) * 64, wn = (wid & 3) * 32;
    const int g = lane >> 2, tg = lane & 3;

    // loader geometry: thread -> (row, hi/lo half)
    const int lr   = tid >> 1;
    const int half = tid & 1;
    const int arow = min(m0 + lr, M - 1);
    const int brow = n0 + lr;
    const uint32_t aRowBase = smemBase + lr * 128;
    const uint32_t bRowBase = smemBase + SB_OFF + lr * 128;
    const int sw = lr & 7;

    float acc[4][4][4];
#pragma unroll
    for (int mt = 0; mt < 4; mt++)
#pragma unroll
        for (int nt = 0; nt < 4; nt++)
#pragma unroll
            for (int i = 0; i < 4; i++) acc[mt][nt][i] = 0.f;

    const int nk = K >> 5;   // # of 32-wide k chunks

    auto load_stage = [&](int buf, int k0) {
        size_t abase;
        if (CAT) abase = ((size_t)(k0 >> 9) * M + arow) * 512 + (k0 & 511);
        else     abase = (size_t)arow * K + k0;
        const __nv_bfloat16* asrc = (half ? Alo : Ahi) + abase;
        const __nv_bfloat16* bsrc = (half ? Blo : Bhi) + (size_t)brow * K + k0;
        uint32_t aBuf = aRowBase + buf * STG_A;
        uint32_t bBuf = bRowBase + buf * STG_A;
#pragma unroll
        for (int j = 0; j < 4; j++) {
            int c = half * 4 + j;
            cpa16s(aBuf + ((c ^ sw) << 4), asrc + j * 8);
        }
#pragma unroll
        for (int j = 0; j < 4; j++) {
            int c = half * 4 + j;
            cpa16s(bBuf + ((c ^ sw) << 4), bsrc + j * 8);
        }
    };

    load_stage(0, 0);
    cpasync_commit();
    load_stage(1, 32);
    cpasync_commit();

    // fragment ldmatrix addresses (row/chunk pattern fixed per thread)
    const int aFr  = (lane & 15);          // A: row offset within 16
    const int aCh  = (lane >> 4);          // A: k-chunk offset (0/1)
    const int bFr  = (lane & 7) + ((lane >> 3) & 1) * 8;  // B row offset within 16
    const int bCh  = (lane >> 4);

    int buf = 0;
    for (int it = 0; it < nk; it++) {
        cpasync_wait1();
        __syncthreads();

        if (it + 2 < nk) load_stage((it + 2) % 3, (it + 2) * 32);
        cpasync_commit();

        const uint32_t aStage = smemBase + buf * STG_A;
        const uint32_t bStage = smemBase + SB_OFF + buf * STG_A;

#pragma unroll
        for (int kk8 = 0; kk8 < 4; kk8 += 2) {   // kk = kk8*8 (0, 16)
            // B fragments: 2 ldmatrix.x4 hi, 2 lo -> bh[ntp] = {nt_even_lo, nt_odd_lo, nt_even_hi, nt_odd_hi}
            uint32_t bh[2][4], bl[2][4];
#pragma unroll
            for (int ntp = 0; ntp < 2; ntp++) {
                int r = wn + ntp * 16 + bFr;
                int ch = kk8 + bCh;
                uint32_t base = bStage + r * 128;
                ldsm4(bh[ntp], base + (((ch)     ^ (r & 7)) << 4));
                ldsm4(bl[ntp], base + (((ch + 4) ^ (r & 7)) << 4));
            }
#pragma unroll
            for (int mt = 0; mt < 4; mt++) {
                int r = wm + mt * 16 + aFr;
                int ch = kk8 + aCh;
                uint32_t base = aStage + r * 128;
                uint32_t ah[4], al[4];
                ldsm4(ah, base + (((ch)     ^ (r & 7)) << 4));
                ldsm4(al, base + (((ch + 4) ^ (r & 7)) << 4));
#pragma unroll
                for (int nt = 0; nt < 4; nt++) {
                    int p = nt >> 1, q = nt & 1;
                    mma_bf16(acc[mt][nt], ah, bh[p][q], bh[p][2 + q]);
                    mma_bf16(acc[mt][nt], ah, bl[p][q], bl[p][2 + q]);
                    mma_bf16(acc[mt][nt], al, bh[p][q], bh[p][2 + q]);
                }
            }
        }
        __syncthreads();
        buf = (buf + 1) % 3;
    }

    // epilogue
#pragma unroll
    for (int mt = 0; mt < 4; mt++) {
        int r = m0 + wm + mt * 16 + g;
#pragma unroll
        for (int nt = 0; nt < 4; nt++) {
            int c = n0 + wn + nt * 8 + 2 * tg;
            float b0 = bias[c], b1 = bias[c + 1];
            if (r < M) {
                float v0 = acc[mt][nt][0] + b0;
                float v1 = acc[mt][nt][1] + b1;
                if (RELU) { v0 = fmaxf(v0, 0.f); v1 = fmaxf(v1, 0.f); }
                *(float2*)&C[(size_t)r * N + c] = make_float2(v0, v1);
            }
            if (r + 8 < M) {
                float v2 = acc[mt][nt][2] + b0;
                float v3 = acc[mt][nt][3] + b1;
                if (RELU) { v2 = fmaxf(v2, 0.f); v3 = fmaxf(v3, 0.f); }
                *(float2*)&C[(size_t)(r + 8) * N + c] = make_float2(v2, v3);
            }
        }
    }
}

// =================================================================
// BatchNorm: deterministic two-pass stats + apply(+relu) -> split bf16
// =================================================================
__global__ __launch_bounds__(256) void bn_partial(
    const float* __restrict__ h, float* __restrict__ ps, float* __restrict__ pq)
{
    int chunk = blockIdx.x;
    int b     = blockIdx.y;
    int tid   = threadIdx.x;
    int n0    = chunk * 64;
    int rows  = min(64, NN - n0);
    const float* base = h + ((size_t)b * NN + n0) * HD;

    float s0 = 0.f, q0 = 0.f, s1 = 0.f, q1 = 0.f;
    for (int r = 0; r < rows; r++) {
        float v0 = base[(size_t)r * HD + tid];
        float v1 = base[(size_t)r * HD + tid + 256];
        s0 += v0; q0 += v0 * v0;
        s1 += v1; q1 += v1 * v1;
    }
    size_t o = ((size_t)b * NCHUNK + chunk) * HD;
    ps[o + tid]       = s0;
    ps[o + tid + 256] = s1;
    pq[o + tid]       = q0;
    pq[o + tid + 256] = q1;
}

__global__ __launch_bounds__(512) void bn_finalize(
    const float* __restrict__ ps, const float* __restrict__ pq,
    const float* __restrict__ g, const float* __restrict__ be,
    float* __restrict__ scale, float* __restrict__ shift)
{
    int b = blockIdx.x;
    int c = threadIdx.x;
    float s = 0.f, q = 0.f;
    for (int j = 0; j < NCHUNK; j++) {
        size_t o = ((size_t)b * NCHUNK + j) * HD + c;
        s += ps[o];
        q += pq[o];
    }
    float mean = s * (1.0f / NN);
    float var  = fmaxf(q * (1.0f / NN) - mean * mean, 0.f);
    float sc   = g[b * HD + c] * rsqrtf(var + 1e-5f);
    scale[b * HD + c] = sc;
    shift[b * HD + c] = be[b * HD + c] - mean * sc;
}

__global__ __launch_bounds__(256) void bn_apply_relu_split(
    const float* __restrict__ h, const float* __restrict__ scale,
    const float* __restrict__ shift,
    __nv_bfloat16* __restrict__ ohi, __nv_bfloat16* __restrict__ olo)
{
    size_t i4 = (size_t)blockIdx.x * blockDim.x + threadIdx.x;
    size_t e  = i4 * 4;
    int c = (int)(e & (HD - 1));
    int b = (int)(e / ((size_t)NN * HD));
    const float* sc = scale + b * HD + c;
    const float* sh = shift + b * HD + c;
    float4 v = *(const float4*)(h + e);
    float r0 = fmaxf(v.x * sc[0] + sh[0], 0.f);
    float r1 = fmaxf(v.y * sc[1] + sh[1], 0.f);
    float r2 = fmaxf(v.z * sc[2] + sh[2], 0.f);
    float r3 = fmaxf(v.w * sc[3] + sh[3], 0.f);
    __nv_bfloat16 h0, h1, h2, h3, l0, l1, l2, l3;
    splitf(r0, h0, l0); splitf(r1, h1, l1);
    splitf(r2, h2, l2); splitf(r3, h3, l3);
    __nv_bfloat162* ph = (__nv_bfloat162*)(ohi + e);
    __nv_bfloat162* pl = (__nv_bfloat162*)(olo + e);
    ph[0] = __nv_bfloat162(h0, h1); ph[1] = __nv_bfloat162(h2, h3);
    pl[0] = __nv_bfloat162(l0, l1); pl[1] = __nv_bfloat162(l2, l3);
}

// =================================================================
// KAN
// =================================================================
__device__ __forceinline__ void kan_bases(float x, float* out9)
{
    out9[0] = x / (1.0f + expf(-x));
    float b[11];
#pragma unroll
    for (int j = 0; j < 11; j++) {
        float gj  = (float)(j - 3) * 0.4f - 1.0f;
        float gj1 = (float)(j - 2) * 0.4f - 1.0f;
        b[j] = (x >= gj && x < gj1) ? 1.0f : 0.0f;
    }
#pragma unroll
    for (int p = 1; p <= 3; p++) {
        float inv = 1.0f / (0.4f * (float)p);
#pragma unroll
        for (int j = 0; j < 10; j++) {
            if (j < 11 - p) {
                float gj   = (float)(j - 3) * 0.4f - 1.0f;
                float gjp1 = (float)(j + p - 2) * 0.4f - 1.0f;
                b[j] = (x - gj) * inv * b[j] + (gjp1 - x) * inv * b[j + 1];
            }
        }
    }
#pragma unroll
    for (int j = 0; j < 8; j++) out9[1 + j] = b[j];
}

__global__ __launch_bounds__(256) void kan1_prep(
    const float* __restrict__ bw1, const float* __restrict__ sw1,
    const float* __restrict__ sc1, float* __restrict__ wAll)
{
    int idx = blockIdx.x * 256 + threadIdx.x;
    if (idx >= F1 * 9 * 32) return;
    int o = idx & 31;
    int t = idx >> 5;
    int c = t % 9;
    int i = t / 9;
    wAll[idx] = (c == 0) ? bw1[o * F1 + i]
                         : sw1[(o * F1 + i) * 8 + (c - 1)] * sc1[o * F1 + i];
}

__global__ __launch_bounds__(256) void kan1_kernel(
    const float* __restrict__ f, const float* __restrict__ wAll, float* __restrict__ f2)
{
    __shared__ float xs[32][16];
    __shared__ float augS[16 * 9][32];
    __shared__ float wS[16 * 9][32];

    int tid = threadIdx.x;
    int n0  = blockIdx.x * 32;
    int tx  = tid & 15;
    int ty  = tid >> 4;

    float a00 = 0.f, a01 = 0.f, a10 = 0.f, a11 = 0.f;

    for (int i0 = 0; i0 < F1; i0 += 16) {
        __syncthreads();
        if (tid < 128) {
            int r  = tid >> 2;
            int c4 = (tid & 3) * 4;
            *(float4*)&xs[r][c4] =
                *(const float4*)(f + (size_t)(n0 + r) * F1 + i0 + c4);
        }
        {
            const float4* src = (const float4*)(wAll + (size_t)i0 * 9 * 32);
            float4* dst = (float4*)&wS[0][0];
            for (int q = tid; q < (16 * 9 * 32) / 4; q += 256) dst[q] = src[q];
        }
        __syncthreads();
#pragma unroll
        for (int j = 0; j < 2; j++) {
            int p  = tid + j * 256;
            int r  = p & 31;
            int ci = p >> 5;
            float out9[9];
            kan_bases(xs[r][ci], out9);
#pragma unroll
            for (int c = 0; c < 9; c++) augS[ci * 9 + c][r] = out9[c];
        }
        __syncthreads();
#pragma unroll 4
        for (int kk = 0; kk < 16 * 9; kk++) {
            float x0 = augS[kk][ty], x1 = augS[kk][ty + 16];
            float w0 = wS[kk][tx],   w1 = wS[kk][tx + 16];
            a00 += x0 * w0; a01 += x0 * w1;
            a10 += x1 * w0; a11 += x1 * w1;
        }
    }

    f2[(size_t)(n0 + ty) * 32 + tx]           = a00;
    f2[(size_t)(n0 + ty) * 32 + tx + 16]      = a01;
    f2[(size_t)(n0 + ty + 16) * 32 + tx]      = a10;
    f2[(size_t)(n0 + ty + 16) * 32 + tx + 16] = a11;
}

__global__ __launch_bounds__(256) void kan2_kernel(
    const float* __restrict__ f2,
    const float* __restrict__ bw2, const float* __restrict__ sw2,
    const float* __restrict__ sc2, float* __restrict__ out)
{
    __shared__ float wS[10 * 32 * 9];
    for (int q = threadIdx.x; q < 10 * 32 * 9; q += 256) {
        int o = q / 288;
        int r = q % 288;
        int i = r / 9;
        int c = r % 9;
        wS[q] = (c == 0) ? bw2[o * 32 + i]
                         : sw2[(o * 32 + i) * 8 + (c - 1)] * sc2[o * 32 + i];
    }
    __syncthreads();

    int n = blockIdx.x * 256 + threadIdx.x;
    if (n >= NN) return;

    float xin[32];
#pragma unroll
    for (int q = 0; q < 8; q++)
        *(float4*)&xin[q * 4] = *(const float4*)(f2 + (size_t)n * 32 + q * 4);

    float acc[10];
#pragma unroll
    for (int o = 0; o < 10; o++) acc[o] = 0.f;

    for (int i = 0; i < 32; i++) {
        float out9[9];
        kan_bases(xin[i], out9);
#pragma unroll
        for (int o = 0; o < 10; o++) {
            const float* w = &wS[o * 288 + i * 9];
#pragma unroll
            for (int c = 0; c < 9; c++) acc[o] += out9[c] * w[c];
        }
    }
#pragma unroll
    for (int o = 0; o < 10; o++) out[(size_t)n * 10 + o] = acc[o];
}

// =================================================================
// launch
// =================================================================
extern "C" void kernel_launch(void* const* d_in, const int* in_sizes, int n_in,
                              void* d_out, int out_size)
{
    const float* x   = (const float*)d_in[0];
    const float* W1  = (const float*)d_in[3];
    const float* b1  = (const float*)d_in[4];
    const float* g1  = (const float*)d_in[5];
    const float* be1 = (const float*)d_in[6];
    const float* W2  = (const float*)d_in[7];
    const float* b2  = (const float*)d_in[8];
    const float* g2  = (const float*)d_in[9];
    const float* be2 = (const float*)d_in[10];
    const float* Wf  = (const float*)d_in[11];
    const float* bf  = (const float*)d_in[12];
    const float* bw1 = (const float*)d_in[13];
    const float* sw1 = (const float*)d_in[14];
    const float* sc1 = (const float*)d_in[15];
    const float* bw2 = (const float*)d_in[16];
    const float* sw2 = (const float*)d_in[17];
    const float* sc2 = (const float*)d_in[18];
    float* out = (float*)d_out;

    float *hfp, *fp, *f2p, *psp, *pqp, *scp, *shp, *wallp;
    __nv_bfloat16 *h1hi, *h1lo, *h2hi, *h2lo, *xhi, *xlo;
    __nv_bfloat16 *w1hi, *w1lo, *w2hi, *w2lo, *wfhi, *wflo;
    cudaGetSymbolAddress((void**)&hfp,   d_hf);
    cudaGetSymbolAddress((void**)&fp,    d_f);
    cudaGetSymbolAddress((void**)&f2p,   d_f2);
    cudaGetSymbolAddress((void**)&psp,   d_ps);
    cudaGetSymbolAddress((void**)&pqp,   d_pq);
    cudaGetSymbolAddress((void**)&scp,   d_scale);
    cudaGetSymbolAddress((void**)&shp,   d_shift);
    cudaGetSymbolAddress((void**)&wallp, d_wall);
    cudaGetSymbolAddress((void**)&h1hi,  d_h1hi);
    cudaGetSymbolAddress((void**)&h1lo,  d_h1lo);
    cudaGetSymbolAddress((void**)&h2hi,  d_h2hi);
    cudaGetSymbolAddress((void**)&h2lo,  d_h2lo);
    cudaGetSymbolAddress((void**)&xhi,   d_xhi);
    cudaGetSymbolAddress((void**)&xlo,   d_xlo);
    cudaGetSymbolAddress((void**)&w1hi,  d_w1hi);
    cudaGetSymbolAddress((void**)&w1lo,  d_w1lo);
    cudaGetSymbolAddress((void**)&w2hi,  d_w2hi);
    cudaGetSymbolAddress((void**)&w2lo,  d_w2lo);
    cudaGetSymbolAddress((void**)&wfhi,  d_wfhi);
    cudaGetSymbolAddress((void**)&wflo,  d_wflo);

    const int SMEM = 2 * 3 * 128 * 64 * 2;   // 98304 B
    cudaFuncSetAttribute(mma_gemm<false, false>,
                         cudaFuncAttributeMaxDynamicSharedMemorySize, SMEM);
    cudaFuncSetAttribute(mma_gemm<true, true>,
                         cudaFuncAttributeMaxDynamicSharedMemorySize, SMEM);

    // ---- prep ----
    split_kernel<<<(BB * NN * FEAT / 4) / 256, 256>>>(x, xhi, xlo);
    tsplit_kernel<<<dim3(HD / 32, FEAT / 32, BB), 256>>>(W1, w1hi, w1lo, FEAT, HD);
    tsplit_kernel<<<dim3(HD / 32, HD / 32, BB),   256>>>(W2, w2hi, w2lo, HD, HD);
    tsplit_kernel<<<dim3(F1 / 32, CATK / 32, 1),  256>>>(Wf, wfhi, wflo, CATK, F1);
    kan1_prep<<<(F1 * 9 * 32 + 255) / 256, 256>>>(bw1, sw1, sc1, wallp);

    dim3 gemm12_grid(HD / 128, (NN + 127) / 128, BB);
    dim3 gemm3_grid(F1 / 128, (NN + 127) / 128, 1);
    dim3 bn_grid(NCHUNK, BB);

    // layer 1
    mma_gemm<false, false><<<gemm12_grid, 256, SMEM>>>(xhi, xlo, w1hi, w1lo, b1, hfp, NN, HD, FEAT);
    bn_partial<<<bn_grid, 256>>>(hfp, psp, pqp);
    bn_finalize<<<BB, 512>>>(psp, pqp, g1, be1, scp, shp);
    bn_apply_relu_split<<<(BB * NN * HD / 4) / 256, 256>>>(hfp, scp, shp, h1hi, h1lo);

    // layer 2
    mma_gemm<false, false><<<gemm12_grid, 256, SMEM>>>(h1hi, h1lo, w2hi, w2lo, b2, hfp, NN, HD, HD);
    bn_partial<<<bn_grid, 256>>>(hfp, psp, pqp);
    bn_finalize<<<BB, 512>>>(psp, pqp, g2, be2, scp, shp);
    bn_apply_relu_split<<<(BB * NN * HD / 4) / 256, 256>>>(hfp, scp, shp, h2hi, h2lo);

    // feature layer (concat folded into A-gather)
    mma_gemm<true, true><<<gemm3_grid, 256, SMEM>>>(h2hi, h2lo, wfhi, wflo, bf, fp, NN, F1, CATK);

    // KAN
    kan1_kernel<<<NN / 32, 256>>>(fp, wallp, f2p);
    kan2_kernel<<<(NN + 255) / 256, 256>>>(f2p, bw2, sw2, sc2, out);
}

// round 6
// speedup vs baseline: 1.1845x; 1.1845x over previous
#include <cuda_runtime.h>
#include <cuda_bf16.h>
#include <math.h>
#include <stdint.h>

// ---------------- problem constants ----------------
#define BB   8
#define NN   20000
#define FEAT 256
#define HD   512
#define CATK 4096      // BB*HD
#define F1   1024
#define NCHUNK 313     // ceil(20000/64)

// ---------------- GEMM smem layout (double-buffered, dynamic) ----------------
#define PITCH     40                  // bf16 elements per row (80 B)
#define ARR_BYTES (128 * PITCH * 2)   // 10240 B per logical array
#define OFF_AH    0
#define OFF_AL    (1 * ARR_BYTES)
#define OFF_BH    (2 * ARR_BYTES)
#define OFF_BL    (3 * ARR_BYTES)
#define STG_BYTES (4 * ARR_BYTES)     // 40960 B per stage
#define DYN_SMEM  (2 * STG_BYTES)     // 81920 B

// ---------------- scratch ----------------
__device__ float          d_hf[BB * NN * HD];
__device__ __nv_bfloat16  d_h1hi[BB * NN * HD];
__device__ __nv_bfloat16  d_h1lo[BB * NN * HD];
__device__ __nv_bfloat16  d_h2hi[BB * NN * HD];
__device__ __nv_bfloat16  d_h2lo[BB * NN * HD];
__device__ __nv_bfloat16  d_xhi[BB * NN * FEAT];
__device__ __nv_bfloat16  d_xlo[BB * NN * FEAT];
__device__ __nv_bfloat16  d_w1hi[BB * HD * FEAT];
__device__ __nv_bfloat16  d_w1lo[BB * HD * FEAT];
__device__ __nv_bfloat16  d_w2hi[BB * HD * HD];
__device__ __nv_bfloat16  d_w2lo[BB * HD * HD];
__device__ __nv_bfloat16  d_wfhi[F1 * CATK];
__device__ __nv_bfloat16  d_wflo[F1 * CATK];
__device__ float d_f [NN * F1];
__device__ float d_f2[NN * 32];
__device__ float d_ps[BB * NCHUNK * HD];
__device__ float d_pq[BB * NCHUNK * HD];
__device__ float d_scale[BB * HD];
__device__ float d_shift[BB * HD];
__device__ float d_wall[F1 * 9 * 32];

// ---------------- helpers ----------------
__device__ __forceinline__ void splitf(float v, __nv_bfloat16& h, __nv_bfloat16& l) {
    h = __float2bfloat16(v);
    l = __float2bfloat16(v - __bfloat162float(h));
}

__device__ __forceinline__ void cpa16s(uint32_t saddr, const void* g) {
    asm volatile("cp.async.cg.shared.global [%0], [%1], 16;" :: "r"(saddr), "l"(g));
}
__device__ __forceinline__ void cpasync_commit() {
    asm volatile("cp.async.commit_group;" ::: "memory");
}

__device__ __forceinline__ void mma_bf16(float (&c)[4], const uint32_t (&a)[4],
                                         uint32_t b0, uint32_t b1) {
    asm volatile(
        "mma.sync.aligned.m16n8k16.row.col.f32.bf16.bf16.f32 "
        "{%0,%1,%2,%3}, {%4,%5,%6,%7}, {%8,%9}, {%0,%1,%2,%3};\n"
        : "+f"(c[0]), "+f"(c[1]), "+f"(c[2]), "+f"(c[3])
        : "r"(a[0]), "r"(a[1]), "r"(a[2]), "r"(a[3]), "r"(b0), "r"(b1));
}

// =================================================================
// split / transpose-split prep
// =================================================================
__global__ __launch_bounds__(256) void split_kernel(
    const float* __restrict__ src, __nv_bfloat16* __restrict__ hi,
    __nv_bfloat16* __restrict__ lo)
{
    size_t i = ((size_t)blockIdx.x * 256 + threadIdx.x) * 4;
    float4 v = *(const float4*)(src + i);
    __nv_bfloat16 h0, h1, h2, h3, l0, l1, l2, l3;
    splitf(v.x, h0, l0); splitf(v.y, h1, l1);
    splitf(v.z, h2, l2); splitf(v.w, h3, l3);
    __nv_bfloat162* ph = (__nv_bfloat162*)(hi + i);
    __nv_bfloat162* pl = (__nv_bfloat162*)(lo + i);
    ph[0] = __nv_bfloat162(h0, h1); ph[1] = __nv_bfloat162(h2, h3);
    pl[0] = __nv_bfloat162(l0, l1); pl[1] = __nv_bfloat162(l2, l3);
}

__global__ __launch_bounds__(256) void tsplit_kernel(
    const float* __restrict__ W, __nv_bfloat16* __restrict__ Thi,
    __nv_bfloat16* __restrict__ Tlo, int K, int N)
{
    __shared__ float t[32][33];
    int b = blockIdx.z;
    W   += (size_t)b * K * N;
    Thi += (size_t)b * N * K;
    Tlo += (size_t)b * N * K;
    int n0 = blockIdx.x * 32, k0 = blockIdx.y * 32;
    int tx = threadIdx.x & 31, ty = threadIdx.x >> 5;
#pragma unroll
    for (int i = 0; i < 4; i++)
        t[ty + i * 8][tx] = W[(size_t)(k0 + ty + i * 8) * N + n0 + tx];
    __syncthreads();
#pragma unroll
    for (int i = 0; i < 4; i++) {
        float v = t[tx][ty + i * 8];
        __nv_bfloat16 h, l;
        splitf(v, h, l);
        size_t o = (size_t)(n0 + ty + i * 8) * K + k0 + tx;
        Thi[o] = h;
        Tlo[o] = l;
    }
}

// =================================================================
// HMMA bf16-split GEMM: C[b] = A[b] @ B[b]^T + bias, 128x128x32 tiles,
// DOUBLE-BUFFERED cp.async (prefetch next chunk during compute).
// Inner loop identical to the validated R3 kernel.
// =================================================================
template<bool CAT, bool RELU>
__global__ __launch_bounds__(256, 2) void mma_gemm(
    const __nv_bfloat16* __restrict__ Ahi, const __nv_bfloat16* __restrict__ Alo,
    const __nv_bfloat16* __restrict__ Bhi, const __nv_bfloat16* __restrict__ Blo,
    const float* __restrict__ bias, float* __restrict__ C,
    int M, int N, int K)
{
    extern __shared__ __align__(16) char smem_raw[];
    const uint32_t smemBase = (uint32_t)__cvta_generic_to_shared(smem_raw);

    int b = blockIdx.z;
    if (!CAT) {
        Ahi += (size_t)b * M * K;
        Alo += (size_t)b * M * K;
    }
    Bhi  += (size_t)b * N * K;
    Blo  += (size_t)b * N * K;
    bias += (size_t)b * N;
    C    += (size_t)b * M * N;

    const int tid  = threadIdx.x;
    const int m0   = blockIdx.y * 128, n0 = blockIdx.x * 128;
    const int lrow = tid >> 1;
    const int lcol = (tid & 1) * 16;

    const int wid = tid >> 5, lane = tid & 31;
    const int wm = (wid >> 2) * 64, wn = (wid & 3) * 32;
    const int g = lane >> 2, tg = lane & 3;

    float acc[4][4][4];
#pragma unroll
    for (int mt = 0; mt < 4; mt++)
#pragma unroll
        for (int nt = 0; nt < 4; nt++)
#pragma unroll
            for (int i = 0; i < 4; i++) acc[mt][nt][i] = 0.f;

    const int  arow = min(m0 + lrow, M - 1);   // clamp; invalid rows discarded at store
    const int  brow = n0 + lrow;
    const uint32_t lOff = (uint32_t)(lrow * PITCH + lcol) * 2;

    const int nk = K >> 5;

    auto load_stage = [&](int stg, int k0) {
        size_t abase;
        if (CAT) abase = ((size_t)(k0 >> 9) * M + arow) * 512 + (k0 & 511);
        else     abase = (size_t)arow * K + k0;
        const __nv_bfloat16* pah = Ahi + abase + lcol;
        const __nv_bfloat16* pal = Alo + abase + lcol;
        const __nv_bfloat16* pbh = Bhi + (size_t)brow * K + k0 + lcol;
        const __nv_bfloat16* pbl = Blo + (size_t)brow * K + k0 + lcol;
        uint32_t st = smemBase + stg * STG_BYTES + lOff;
        cpa16s(st + OFF_AH,      pah);
        cpa16s(st + OFF_AH + 16, pah + 8);
        cpa16s(st + OFF_AL,      pal);
        cpa16s(st + OFF_AL + 16, pal + 8);
        cpa16s(st + OFF_BH,      pbh);
        cpa16s(st + OFF_BH + 16, pbh + 8);
        cpa16s(st + OFF_BL,      pbl);
        cpa16s(st + OFF_BL + 16, pbl + 8);
        cpasync_commit();
    };

    load_stage(0, 0);

    for (int it = 0; it < nk; it++) {
        if (it + 1 < nk) {
            load_stage((it + 1) & 1, (it + 1) * 32);
            asm volatile("cp.async.wait_group 1;" ::: "memory");
        } else {
            asm volatile("cp.async.wait_group 0;" ::: "memory");
        }
        __syncthreads();

        const char* stgp = smem_raw + (it & 1) * STG_BYTES;
        const __nv_bfloat16* pAh = (const __nv_bfloat16*)(stgp + OFF_AH);
        const __nv_bfloat16* pAl = (const __nv_bfloat16*)(stgp + OFF_AL);
        const __nv_bfloat16* pBh = (const __nv_bfloat16*)(stgp + OFF_BH);
        const __nv_bfloat16* pBl = (const __nv_bfloat16*)(stgp + OFF_BL);

#pragma unroll
        for (int kk = 0; kk < 32; kk += 16) {
            uint32_t ah[4][4], al[4][4], bh[4][2], bl[4][2];
#pragma unroll
            for (int mt = 0; mt < 4; mt++) {
                int r = wm + mt * 16 + g;
                ah[mt][0] = *(const uint32_t*)&pAh[(r    ) * PITCH + kk + 2 * tg];
                ah[mt][1] = *(const uint32_t*)&pAh[(r + 8) * PITCH + kk + 2 * tg];
                ah[mt][2] = *(const uint32_t*)&pAh[(r    ) * PITCH + kk + 2 * tg + 8];
                ah[mt][3] = *(const uint32_t*)&pAh[(r + 8) * PITCH + kk + 2 * tg + 8];
                al[mt][0] = *(const uint32_t*)&pAl[(r    ) * PITCH + kk + 2 * tg];
                al[mt][1] = *(const uint32_t*)&pAl[(r + 8) * PITCH + kk + 2 * tg];
                al[mt][2] = *(const uint32_t*)&pAl[(r    ) * PITCH + kk + 2 * tg + 8];
                al[mt][3] = *(const uint32_t*)&pAl[(r + 8) * PITCH + kk + 2 * tg + 8];
            }
#pragma unroll
            for (int nt = 0; nt < 4; nt++) {
                int n = wn + nt * 8 + g;
                bh[nt][0] = *(const uint32_t*)&pBh[n * PITCH + kk + 2 * tg];
                bh[nt][1] = *(const uint32_t*)&pBh[n * PITCH + kk + 2 * tg + 8];
                bl[nt][0] = *(const uint32_t*)&pBl[n * PITCH + kk + 2 * tg];
                bl[nt][1] = *(const uint32_t*)&pBl[n * PITCH + kk + 2 * tg + 8];
            }
#pragma unroll
            for (int mt = 0; mt < 4; mt++)
#pragma unroll
                for (int nt = 0; nt < 4; nt++) {
                    mma_bf16(acc[mt][nt], ah[mt], bh[nt][0], bh[nt][1]);
                    mma_bf16(acc[mt][nt], ah[mt], bl[nt][0], bl[nt][1]);
                    mma_bf16(acc[mt][nt], al[mt], bh[nt][0], bh[nt][1]);
                }
        }
        __syncthreads();
    }

    // epilogue
#pragma unroll
    for (int mt = 0; mt < 4; mt++) {
        int r = m0 + wm + mt * 16 + g;
#pragma unroll
        for (int nt = 0; nt < 4; nt++) {
            int c = n0 + wn + nt * 8 + 2 * tg;
            float b0 = bias[c], b1 = bias[c + 1];
            if (r < M) {
                float v0 = acc[mt][nt][0] + b0;
                float v1 = acc[mt][nt][1] + b1;
                if (RELU) { v0 = fmaxf(v0, 0.f); v1 = fmaxf(v1, 0.f); }
                *(float2*)&C[(size_t)r * N + c] = make_float2(v0, v1);
            }
            if (r + 8 < M) {
                float v2 = acc[mt][nt][2] + b0;
                float v3 = acc[mt][nt][3] + b1;
                if (RELU) { v2 = fmaxf(v2, 0.f); v3 = fmaxf(v3, 0.f); }
                *(float2*)&C[(size_t)(r + 8) * N + c] = make_float2(v2, v3);
            }
        }
    }
}

// =================================================================
// BatchNorm: deterministic two-pass stats + apply(+relu) -> split bf16
// =================================================================
__global__ __launch_bounds__(256) void bn_partial(
    const float* __restrict__ h, float* __restrict__ ps, float* __restrict__ pq)
{
    int chunk = blockIdx.x;
    int b     = blockIdx.y;
    int tid   = threadIdx.x;
    int n0    = chunk * 64;
    int rows  = min(64, NN - n0);
    const float* base = h + ((size_t)b * NN + n0) * HD;

    float s0 = 0.f, q0 = 0.f, s1 = 0.f, q1 = 0.f;
    for (int r = 0; r < rows; r++) {
        float v0 = base[(size_t)r * HD + tid];
        float v1 = base[(size_t)r * HD + tid + 256];
        s0 += v0; q0 += v0 * v0;
        s1 += v1; q1 += v1 * v1;
    }
    size_t o = ((size_t)b * NCHUNK + chunk) * HD;
    ps[o + tid]       = s0;
    ps[o + tid + 256] = s1;
    pq[o + tid]       = q0;
    pq[o + tid + 256] = q1;
}

__global__ __launch_bounds__(512) void bn_finalize(
    const float* __restrict__ ps, const float* __restrict__ pq,
    const float* __restrict__ g, const float* __restrict__ be,
    float* __restrict__ scale, float* __restrict__ shift)
{
    int b = blockIdx.x;
    int c = threadIdx.x;
    float s = 0.f, q = 0.f;
    for (int j = 0; j < NCHUNK; j++) {
        size_t o = ((size_t)b * NCHUNK + j) * HD + c;
        s += ps[o];
        q += pq[o];
    }
    float mean = s * (1.0f / NN);
    float var  = fmaxf(q * (1.0f / NN) - mean * mean, 0.f);
    float sc   = g[b * HD + c] * rsqrtf(var + 1e-5f);
    scale[b * HD + c] = sc;
    shift[b * HD + c] = be[b * HD + c] - mean * sc;
}

__global__ __launch_bounds__(256) void bn_apply_relu_split(
    const float* __restrict__ h, const float* __restrict__ scale,
    const float* __restrict__ shift,
    __nv_bfloat16* __restrict__ ohi, __nv_bfloat16* __restrict__ olo)
{
    size_t i4 = (size_t)blockIdx.x * blockDim.x + threadIdx.x;
    size_t e  = i4 * 4;
    int c = (int)(e & (HD - 1));
    int b = (int)(e / ((size_t)NN * HD));
    const float* sc = scale + b * HD + c;
    const float* sh = shift + b * HD + c;
    float4 v = *(const float4*)(h + e);
    float r0 = fmaxf(v.x * sc[0] + sh[0], 0.f);
    float r1 = fmaxf(v.y * sc[1] + sh[1], 0.f);
    float r2 = fmaxf(v.z * sc[2] + sh[2], 0.f);
    float r3 = fmaxf(v.w * sc[3] + sh[3], 0.f);
    __nv_bfloat16 h0, h1, h2, h3, l0, l1, l2, l3;
    splitf(r0, h0, l0); splitf(r1, h1, l1);
    splitf(r2, h2, l2); splitf(r3, h3, l3);
    __nv_bfloat162* ph = (__nv_bfloat162*)(ohi + e);
    __nv_bfloat162* pl = (__nv_bfloat162*)(olo + e);
    ph[0] = __nv_bfloat162(h0, h1); ph[1] = __nv_bfloat162(h2, h3);
    pl[0] = __nv_bfloat162(l0, l1); pl[1] = __nv_bfloat162(l2, l3);
}

// =================================================================
// KAN
// =================================================================
__device__ __forceinline__ void kan_bases(float x, float* out9)
{
    out9[0] = x / (1.0f + expf(-x));
    float b[11];
#pragma unroll
    for (int j = 0; j < 11; j++) {
        float gj  = (float)(j - 3) * 0.4f - 1.0f;
        float gj1 = (float)(j - 2) * 0.4f - 1.0f;
        b[j] = (x >= gj && x < gj1) ? 1.0f : 0.0f;
    }
#pragma unroll
    for (int p = 1; p <= 3; p++) {
        float inv = 1.0f / (0.4f * (float)p);
#pragma unroll
        for (int j = 0; j < 10; j++) {
            if (j < 11 - p) {
                float gj   = (float)(j - 3) * 0.4f - 1.0f;
                float gjp1 = (float)(j + p - 2) * 0.4f - 1.0f;
                b[j] = (x - gj) * inv * b[j] + (gjp1 - x) * inv * b[j + 1];
            }
        }
    }
#pragma unroll
    for (int j = 0; j < 8; j++) out9[1 + j] = b[j];
}

__global__ __launch_bounds__(256) void kan1_prep(
    const float* __restrict__ bw1, const float* __restrict__ sw1,
    const float* __restrict__ sc1, float* __restrict__ wAll)
{
    int idx = blockIdx.x * 256 + threadIdx.x;
    if (idx >= F1 * 9 * 32) return;
    int o = idx & 31;
    int t = idx >> 5;
    int c = t % 9;
    int i = t / 9;
    wAll[idx] = (c == 0) ? bw1[o * F1 + i]
                         : sw1[(o * F1 + i) * 8 + (c - 1)] * sc1[o * F1 + i];
}

__global__ __launch_bounds__(256) void kan1_kernel(
    const float* __restrict__ f, const float* __restrict__ wAll, float* __restrict__ f2)
{
    __shared__ float xs[32][16];
    __shared__ float augS[16 * 9][32];
    __shared__ float wS[16 * 9][32];

    int tid = threadIdx.x;
    int n0  = blockIdx.x * 32;
    int tx  = tid & 15;
    int ty  = tid >> 4;

    float a00 = 0.f, a01 = 0.f, a10 = 0.f, a11 = 0.f;

    for (int i0 = 0; i0 < F1; i0 += 16) {
        __syncthreads();
        if (tid < 128) {
            int r  = tid >> 2;
            int c4 = (tid & 3) * 4;
            *(float4*)&xs[r][c4] =
                *(const float4*)(f + (size_t)(n0 + r) * F1 + i0 + c4);
        }
        {
            const float4* src = (const float4*)(wAll + (size_t)i0 * 9 * 32);
            float4* dst = (float4*)&wS[0][0];
            for (int q = tid; q < (16 * 9 * 32) / 4; q += 256) dst[q] = src[q];
        }
        __syncthreads();
#pragma unroll
        for (int j = 0; j < 2; j++) {
            int p  = tid + j * 256;
            int r  = p & 31;
            int ci = p >> 5;
            float out9[9];
            kan_bases(xs[r][ci], out9);
#pragma unroll
            for (int c = 0; c < 9; c++) augS[ci * 9 + c][r] = out9[c];
        }
        __syncthreads();
#pragma unroll 4
        for (int kk = 0; kk < 16 * 9; kk++) {
            float x0 = augS[kk][ty], x1 = augS[kk][ty + 16];
            float w0 = wS[kk][tx],   w1 = wS[kk][tx + 16];
            a00 += x0 * w0; a01 += x0 * w1;
            a10 += x1 * w0; a11 += x1 * w1;
        }
    }

    f2[(size_t)(n0 + ty) * 32 + tx]           = a00;
    f2[(size_t)(n0 + ty) * 32 + tx + 16]      = a01;
    f2[(size_t)(n0 + ty + 16) * 32 + tx]      = a10;
    f2[(size_t)(n0 + ty + 16) * 32 + tx + 16] = a11;
}

__global__ __launch_bounds__(256) void kan2_kernel(
    const float* __restrict__ f2,
    const float* __restrict__ bw2, const float* __restrict__ sw2,
    const float* __restrict__ sc2, float* __restrict__ out)
{
    __shared__ float wS[10 * 32 * 9];
    for (int q = threadIdx.x; q < 10 * 32 * 9; q += 256) {
        int o = q / 288;
        int r = q % 288;
        int i = r / 9;
        int c = r % 9;
        wS[q] = (c == 0) ? bw2[o * 32 + i]
                         : sw2[(o * 32 + i) * 8 + (c - 1)] * sc2[o * 32 + i];
    }
    __syncthreads();

    int n = blockIdx.x * 256 + threadIdx.x;
    if (n >= NN) return;

    float xin[32];
#pragma unroll
    for (int q = 0; q < 8; q++)
        *(float4*)&xin[q * 4] = *(const float4*)(f2 + (size_t)n * 32 + q * 4);

    float acc[10];
#pragma unroll
    for (int o = 0; o < 10; o++) acc[o] = 0.f;

    for (int i = 0; i < 32; i++) {
        float out9[9];
        kan_bases(xin[i], out9);
#pragma unroll
        for (int o = 0; o < 10; o++) {
            const float* w = &wS[o * 288 + i * 9];
#pragma unroll
            for (int c = 0; c < 9; c++) acc[o] += out9[c] * w[c];
        }
    }
#pragma unroll
    for (int o = 0; o < 10; o++) out[(size_t)n * 10 + o] = acc[o];
}

// =================================================================
// launch
// =================================================================
extern "C" void kernel_launch(void* const* d_in, const int* in_sizes, int n_in,
                              void* d_out, int out_size)
{
    const float* x   = (const float*)d_in[0];
    const float* W1  = (const float*)d_in[3];
    const float* b1  = (const float*)d_in[4];
    const float* g1  = (const float*)d_in[5];
    const float* be1 = (const float*)d_in[6];
    const float* W2  = (const float*)d_in[7];
    const float* b2  = (const float*)d_in[8];
    const float* g2  = (const float*)d_in[9];
    const float* be2 = (const float*)d_in[10];
    const float* Wf  = (const float*)d_in[11];
    const float* bf  = (const float*)d_in[12];
    const float* bw1 = (const float*)d_in[13];
    const float* sw1 = (const float*)d_in[14];
    const float* sc1 = (const float*)d_in[15];
    const float* bw2 = (const float*)d_in[16];
    const float* sw2 = (const float*)d_in[17];
    const float* sc2 = (const float*)d_in[18];
    float* out = (float*)d_out;

    float *hfp, *fp, *f2p, *psp, *pqp, *scp, *shp, *wallp;
    __nv_bfloat16 *h1hi, *h1lo, *h2hi, *h2lo, *xhi, *xlo;
    __nv_bfloat16 *w1hi, *w1lo, *w2hi, *w2lo, *wfhi, *wflo;
    cudaGetSymbolAddress((void**)&hfp,   d_hf);
    cudaGetSymbolAddress((void**)&fp,    d_f);
    cudaGetSymbolAddress((void**)&f2p,   d_f2);
    cudaGetSymbolAddress((void**)&psp,   d_ps);
    cudaGetSymbolAddress((void**)&pqp,   d_pq);
    cudaGetSymbolAddress((void**)&scp,   d_scale);
    cudaGetSymbolAddress((void**)&shp,   d_shift);
    cudaGetSymbolAddress((void**)&wallp, d_wall);
    cudaGetSymbolAddress((void**)&h1hi,  d_h1hi);
    cudaGetSymbolAddress((void**)&h1lo,  d_h1lo);
    cudaGetSymbolAddress((void**)&h2hi,  d_h2hi);
    cudaGetSymbolAddress((void**)&h2lo,  d_h2lo);
    cudaGetSymbolAddress((void**)&xhi,   d_xhi);
    cudaGetSymbolAddress((void**)&xlo,   d_xlo);
    cudaGetSymbolAddress((void**)&w1hi,  d_w1hi);
    cudaGetSymbolAddress((void**)&w1lo,  d_w1lo);
    cudaGetSymbolAddress((void**)&w2hi,  d_w2hi);
    cudaGetSymbolAddress((void**)&w2lo,  d_w2lo);
    cudaGetSymbolAddress((void**)&wfhi,  d_wfhi);
    cudaGetSymbolAddress((void**)&wflo,  d_wflo);

    cudaFuncSetAttribute(mma_gemm<false, false>,
                         cudaFuncAttributeMaxDynamicSharedMemorySize, DYN_SMEM);
    cudaFuncSetAttribute(mma_gemm<true, true>,
                         cudaFuncAttributeMaxDynamicSharedMemorySize, DYN_SMEM);

    // ---- prep ----
    split_kernel<<<(BB * NN * FEAT / 4) / 256, 256>>>(x, xhi, xlo);
    tsplit_kernel<<<dim3(HD / 32, FEAT / 32, BB), 256>>>(W1, w1hi, w1lo, FEAT, HD);
    tsplit_kernel<<<dim3(HD / 32, HD / 32, BB),   256>>>(W2, w2hi, w2lo, HD, HD);
    tsplit_kernel<<<dim3(F1 / 32, CATK / 32, 1),  256>>>(Wf, wfhi, wflo, CATK, F1);
    kan1_prep<<<(F1 * 9 * 32 + 255) / 256, 256>>>(bw1, sw1, sc1, wallp);

    dim3 gemm12_grid(HD / 128, (NN + 127) / 128, BB);
    dim3 gemm3_grid(F1 / 128, (NN + 127) / 128, 1);
    dim3 bn_grid(NCHUNK, BB);

    // layer 1
    mma_gemm<false, false><<<gemm12_grid, 256, DYN_SMEM>>>(xhi, xlo, w1hi, w1lo, b1, hfp, NN, HD, FEAT);
    bn_partial<<<bn_grid, 256>>>(hfp, psp, pqp);
    bn_finalize<<<BB, 512>>>(psp, pqp, g1, be1, scp, shp);
    bn_apply_relu_split<<<(BB * NN * HD / 4) / 256, 256>>>(hfp, scp, shp, h1hi, h1lo);

    // layer 2
    mma_gemm<false, false><<<gemm12_grid, 256, DYN_SMEM>>>(h1hi, h1lo, w2hi, w2lo, b2, hfp, NN, HD, HD);
    bn_partial<<<bn_grid, 256>>>(hfp, psp, pqp);
    bn_finalize<<<BB, 512>>>(psp, pqp, g2, be2, scp, shp);
    bn_apply_relu_split<<<(BB * NN * HD / 4) / 256, 256>>>(hfp, scp, shp, h2hi, h2lo);

    // feature layer (concat folded into A-gather)
    mma_gemm<true, true><<<gemm3_grid, 256, DYN_SMEM>>>(h2hi, h2lo, wfhi, wflo, bf, fp, NN, F1, CATK);

    // KAN
    kan1_kernel<<<NN / 32, 256>>>(fp, wallp, f2p);
    kan2_kernel<<<(NN + 255) / 256, 256>>>(f2p, bw2, sw2, sc2, out);
}

// round 7
// speedup vs baseline: 1.1861x; 1.0014x over previous
#include <cuda_runtime.h>
#include <cuda_bf16.h>
#include <math.h>
#include <stdint.h>

// ---------------- problem constants ----------------
#define BB   8
#define NN   20000
#define FEAT 256
#define HD   512
#define CATK 4096      // BB*HD
#define F1   1024
#define NCHUNK 313     // ceil(20000/64)

// ---------------- GEMM smem layout (double-buffered, dynamic) ----------------
#define PITCH     40                  // bf16 elements per row (80 B)
#define ARR_BYTES (128 * PITCH * 2)   // 10240 B per logical array
#define OFF_AH    0
#define OFF_AL    (1 * ARR_BYTES)
#define OFF_BH    (2 * ARR_BYTES)
#define OFF_BL    (3 * ARR_BYTES)
#define STG_BYTES (4 * ARR_BYTES)     // 40960 B per stage
#define DYN_SMEM  (2 * STG_BYTES)     // 81920 B

// ---------------- scratch ----------------
__device__ float          d_hf[BB * NN * HD];
__device__ __nv_bfloat16  d_h1hi[BB * NN * HD];
__device__ __nv_bfloat16  d_h1lo[BB * NN * HD];
__device__ __nv_bfloat16  d_h2hi[BB * NN * HD];
__device__ __nv_bfloat16  d_h2lo[BB * NN * HD];
__device__ __nv_bfloat16  d_xhi[BB * NN * FEAT];
__device__ __nv_bfloat16  d_xlo[BB * NN * FEAT];
__device__ __nv_bfloat16  d_w1hi[BB * HD * FEAT];
__device__ __nv_bfloat16  d_w1lo[BB * HD * FEAT];
__device__ __nv_bfloat16  d_w2hi[BB * HD * HD];
__device__ __nv_bfloat16  d_w2lo[BB * HD * HD];
__device__ __nv_bfloat16  d_wfhi[F1 * CATK];
__device__ __nv_bfloat16  d_wflo[F1 * CATK];
__device__ float d_f [NN * F1];
__device__ float d_f2[NN * 32];
__device__ float d_ps[BB * NCHUNK * HD];
__device__ float d_pq[BB * NCHUNK * HD];
__device__ float d_scale[BB * HD];
__device__ float d_shift[BB * HD];
__device__ float d_wall[F1 * 9 * 32];

// ---------------- helpers ----------------
__device__ __forceinline__ void splitf(float v, __nv_bfloat16& h, __nv_bfloat16& l) {
    h = __float2bfloat16(v);
    l = __float2bfloat16(v - __bfloat162float(h));
}

__device__ __forceinline__ void cpa16s(uint32_t saddr, const void* g) {
    asm volatile("cp.async.cg.shared.global [%0], [%1], 16;" :: "r"(saddr), "l"(g));
}
__device__ __forceinline__ void cpasync_commit() {
    asm volatile("cp.async.commit_group;" ::: "memory");
}

__device__ __forceinline__ void mma_bf16(float (&c)[4], const uint32_t (&a)[4],
                                         uint32_t b0, uint32_t b1) {
    asm volatile(
        "mma.sync.aligned.m16n8k16.row.col.f32.bf16.bf16.f32 "
        "{%0,%1,%2,%3}, {%4,%5,%6,%7}, {%8,%9}, {%0,%1,%2,%3};\n"
        : "+f"(c[0]), "+f"(c[1]), "+f"(c[2]), "+f"(c[3])
        : "r"(a[0]), "r"(a[1]), "r"(a[2]), "r"(a[3]), "r"(b0), "r"(b1));
}

// =================================================================
// split / transpose-split prep
// =================================================================
__global__ __launch_bounds__(256) void split_kernel(
    const float* __restrict__ src, __nv_bfloat16* __restrict__ hi,
    __nv_bfloat16* __restrict__ lo)
{
    size_t i = ((size_t)blockIdx.x * 256 + threadIdx.x) * 4;
    float4 v = *(const float4*)(src + i);
    __nv_bfloat16 h0, h1, h2, h3, l0, l1, l2, l3;
    splitf(v.x, h0, l0); splitf(v.y, h1, l1);
    splitf(v.z, h2, l2); splitf(v.w, h3, l3);
    __nv_bfloat162* ph = (__nv_bfloat162*)(hi + i);
    __nv_bfloat162* pl = (__nv_bfloat162*)(lo + i);
    ph[0] = __nv_bfloat162(h0, h1); ph[1] = __nv_bfloat162(h2, h3);
    pl[0] = __nv_bfloat162(l0, l1); pl[1] = __nv_bfloat162(l2, l3);
}

__global__ __launch_bounds__(256) void tsplit_kernel(
    const float* __restrict__ W, __nv_bfloat16* __restrict__ Thi,
    __nv_bfloat16* __restrict__ Tlo, int K, int N)
{
    __shared__ float t[32][33];
    int b = blockIdx.z;
    W   += (size_t)b * K * N;
    Thi += (size_t)b * N * K;
    Tlo += (size_t)b * N * K;
    int n0 = blockIdx.x * 32, k0 = blockIdx.y * 32;
    int tx = threadIdx.x & 31, ty = threadIdx.x >> 5;
#pragma unroll
    for (int i = 0; i < 4; i++)
        t[ty + i * 8][tx] = W[(size_t)(k0 + ty + i * 8) * N + n0 + tx];
    __syncthreads();
#pragma unroll
    for (int i = 0; i < 4; i++) {
        float v = t[tx][ty + i * 8];
        __nv_bfloat16 h, l;
        splitf(v, h, l);
        size_t o = (size_t)(n0 + ty + i * 8) * K + k0 + tx;
        Thi[o] = h;
        Tlo[o] = l;
    }
}

// =================================================================
// HMMA bf16-split GEMM: C[b] = A[b] @ B[b]^T + bias, 128x128x32 tiles,
// DOUBLE-BUFFERED cp.async (prefetch next chunk during compute).
// Inner loop identical to the validated R3 kernel.
// =================================================================
template<bool CAT, bool RELU>
__global__ __launch_bounds__(256, 2) void mma_gemm(
    const __nv_bfloat16* __restrict__ Ahi, const __nv_bfloat16* __restrict__ Alo,
    const __nv_bfloat16* __restrict__ Bhi, const __nv_bfloat16* __restrict__ Blo,
    const float* __restrict__ bias, float* __restrict__ C,
    int M, int N, int K)
{
    extern __shared__ __align__(16) char smem_raw[];
    const uint32_t smemBase = (uint32_t)__cvta_generic_to_shared(smem_raw);

    int b = blockIdx.z;
    if (!CAT) {
        Ahi += (size_t)b * M * K;
        Alo += (size_t)b * M * K;
    }
    Bhi  += (size_t)b * N * K;
    Blo  += (size_t)b * N * K;
    bias += (size_t)b * N;
    C    += (size_t)b * M * N;

    const int tid  = threadIdx.x;
    const int m0   = blockIdx.y * 128, n0 = blockIdx.x * 128;
    const int lrow = tid >> 1;
    const int lcol = (tid & 1) * 16;

    const int wid = tid >> 5, lane = tid & 31;
    const int wm = (wid >> 2) * 64, wn = (wid & 3) * 32;
    const int g = lane >> 2, tg = lane & 3;

    float acc[4][4][4];
#pragma unroll
    for (int mt = 0; mt < 4; mt++)
#pragma unroll
        for (int nt = 0; nt < 4; nt++)
#pragma unroll
            for (int i = 0; i < 4; i++) acc[mt][nt][i] = 0.f;

    const int  arow = min(m0 + lrow, M - 1);   // clamp; invalid rows discarded at store
    const int  brow = n0 + lrow;
    const uint32_t lOff = (uint32_t)(lrow * PITCH + lcol) * 2;

    const int nk = K >> 5;

    auto load_stage = [&](int stg, int k0) {
        size_t abase;
        if (CAT) abase = ((size_t)(k0 >> 9) * M + arow) * 512 + (k0 & 511);
        else     abase = (size_t)arow * K + k0;
        const __nv_bfloat16* pah = Ahi + abase + lcol;
        const __nv_bfloat16* pal = Alo + abase + lcol;
        const __nv_bfloat16* pbh = Bhi + (size_t)brow * K + k0 + lcol;
        const __nv_bfloat16* pbl = Blo + (size_t)brow * K + k0 + lcol;
        uint32_t st = smemBase + stg * STG_BYTES + lOff;
        cpa16s(st + OFF_AH,      pah);
        cpa16s(st + OFF_AH + 16, pah + 8);
        cpa16s(st + OFF_AL,      pal);
        cpa16s(st + OFF_AL + 16, pal + 8);
        cpa16s(st + OFF_BH,      pbh);
        cpa16s(st + OFF_BH + 16, pbh + 8);
        cpa16s(st + OFF_BL,      pbl);
        cpa16s(st + OFF_BL + 16, pbl + 8);
        cpasync_commit();
    };

    load_stage(0, 0);

    for (int it = 0; it < nk; it++) {
        if (it + 1 < nk) {
            load_stage((it + 1) & 1, (it + 1) * 32);
            asm volatile("cp.async.wait_group 1;" ::: "memory");
        } else {
            asm volatile("cp.async.wait_group 0;" ::: "memory");
        }
        __syncthreads();

        const char* stgp = smem_raw + (it & 1) * STG_BYTES;
        const __nv_bfloat16* pAh = (const __nv_bfloat16*)(stgp + OFF_AH);
        const __nv_bfloat16* pAl = (const __nv_bfloat16*)(stgp + OFF_AL);
        const __nv_bfloat16* pBh = (const __nv_bfloat16*)(stgp + OFF_BH);
        const __nv_bfloat16* pBl = (const __nv_bfloat16*)(stgp + OFF_BL);

#pragma unroll
        for (int kk = 0; kk < 32; kk += 16) {
            uint32_t ah[4][4], al[4][4], bh[4][2], bl[4][2];
#pragma unroll
            for (int mt = 0; mt < 4; mt++) {
                int r = wm + mt * 16 + g;
                ah[mt][0] = *(const uint32_t*)&pAh[(r    ) * PITCH + kk + 2 * tg];
                ah[mt][1] = *(const uint32_t*)&pAh[(r + 8) * PITCH + kk + 2 * tg];
                ah[mt][2] = *(const uint32_t*)&pAh[(r    ) * PITCH + kk + 2 * tg + 8];
                ah[mt][3] = *(const uint32_t*)&pAh[(r + 8) * PITCH + kk + 2 * tg + 8];
                al[mt][0] = *(const uint32_t*)&pAl[(r    ) * PITCH + kk + 2 * tg];
                al[mt][1] = *(const uint32_t*)&pAl[(r + 8) * PITCH + kk + 2 * tg];
                al[mt][2] = *(const uint32_t*)&pAl[(r    ) * PITCH + kk + 2 * tg + 8];
                al[mt][3] = *(const uint32_t*)&pAl[(r + 8) * PITCH + kk + 2 * tg + 8];
            }
#pragma unroll
            for (int nt = 0; nt < 4; nt++) {
                int n = wn + nt * 8 + g;
                bh[nt][0] = *(const uint32_t*)&pBh[n * PITCH + kk + 2 * tg];
                bh[nt][1] = *(const uint32_t*)&pBh[n * PITCH + kk + 2 * tg + 8];
                bl[nt][0] = *(const uint32_t*)&pBl[n * PITCH + kk + 2 * tg];
                bl[nt][1] = *(const uint32_t*)&pBl[n * PITCH + kk + 2 * tg + 8];
            }
#pragma unroll
            for (int mt = 0; mt < 4; mt++)
#pragma unroll
                for (int nt = 0; nt < 4; nt++) {
                    mma_bf16(acc[mt][nt], ah[mt], bh[nt][0], bh[nt][1]);
                    mma_bf16(acc[mt][nt], ah[mt], bl[nt][0], bl[nt][1]);
                    mma_bf16(acc[mt][nt], al[mt], bh[nt][0], bh[nt][1]);
                }
        }
        __syncthreads();
    }

    // epilogue
#pragma unroll
    for (int mt = 0; mt < 4; mt++) {
        int r = m0 + wm + mt * 16 + g;
#pragma unroll
        for (int nt = 0; nt < 4; nt++) {
            int c = n0 + wn + nt * 8 + 2 * tg;
            float b0 = bias[c], b1 = bias[c + 1];
            if (r < M) {
                float v0 = acc[mt][nt][0] + b0;
                float v1 = acc[mt][nt][1] + b1;
                if (RELU) { v0 = fmaxf(v0, 0.f); v1 = fmaxf(v1, 0.f); }
                *(float2*)&C[(size_t)r * N + c] = make_float2(v0, v1);
            }
            if (r + 8 < M) {
                float v2 = acc[mt][nt][2] + b0;
                float v3 = acc[mt][nt][3] + b1;
                if (RELU) { v2 = fmaxf(v2, 0.f); v3 = fmaxf(v3, 0.f); }
                *(float2*)&C[(size_t)(r + 8) * N + c] = make_float2(v2, v3);
            }
        }
    }
}

// =================================================================
// BatchNorm: deterministic two-pass stats + apply(+relu) -> split bf16
// =================================================================
__global__ __launch_bounds__(256) void bn_partial(
    const float* __restrict__ h, float* __restrict__ ps, float* __restrict__ pq)
{
    int chunk = blockIdx.x;
    int b     = blockIdx.y;
    int tid   = threadIdx.x;
    int n0    = chunk * 64;
    int rows  = min(64, NN - n0);
    const float* base = h + ((size_t)b * NN + n0) * HD;

    float s0 = 0.f, q0 = 0.f, s1 = 0.f, q1 = 0.f;
    for (int r = 0; r < rows; r++) {
        float v0 = base[(size_t)r * HD + tid];
        float v1 = base[(size_t)r * HD + tid + 256];
        s0 += v0; q0 += v0 * v0;
        s1 += v1; q1 += v1 * v1;
    }
    size_t o = ((size_t)b * NCHUNK + chunk) * HD;
    ps[o + tid]       = s0;
    ps[o + tid + 256] = s1;
    pq[o + tid]       = q0;
    pq[o + tid + 256] = q1;
}

__global__ __launch_bounds__(512) void bn_finalize(
    const float* __restrict__ ps, const float* __restrict__ pq,
    const float* __restrict__ g, const float* __restrict__ be,
    float* __restrict__ scale, float* __restrict__ shift)
{
    int b = blockIdx.x;
    int c = threadIdx.x;
    float s = 0.f, q = 0.f;
    for (int j = 0; j < NCHUNK; j++) {
        size_t o = ((size_t)b * NCHUNK + j) * HD + c;
        s += ps[o];
        q += pq[o];
    }
    float mean = s * (1.0f / NN);
    float var  = fmaxf(q * (1.0f / NN) - mean * mean, 0.f);
    float sc   = g[b * HD + c] * rsqrtf(var + 1e-5f);
    scale[b * HD + c] = sc;
    shift[b * HD + c] = be[b * HD + c] - mean * sc;
}

__global__ __launch_bounds__(256) void bn_apply_relu_split(
    const float* __restrict__ h, const float* __restrict__ scale,
    const float* __restrict__ shift,
    __nv_bfloat16* __restrict__ ohi, __nv_bfloat16* __restrict__ olo)
{
    size_t i4 = (size_t)blockIdx.x * blockDim.x + threadIdx.x;
    size_t e  = i4 * 4;
    int c = (int)(e & (HD - 1));
    int b = (int)(e / ((size_t)NN * HD));
    const float* sc = scale + b * HD + c;
    const float* sh = shift + b * HD + c;
    float4 v = *(const float4*)(h + e);
    float r0 = fmaxf(v.x * sc[0] + sh[0], 0.f);
    float r1 = fmaxf(v.y * sc[1] + sh[1], 0.f);
    float r2 = fmaxf(v.z * sc[2] + sh[2], 0.f);
    float r3 = fmaxf(v.w * sc[3] + sh[3], 0.f);
    __nv_bfloat16 h0, h1, h2, h3, l0, l1, l2, l3;
    splitf(r0, h0, l0); splitf(r1, h1, l1);
    splitf(r2, h2, l2); splitf(r3, h3, l3);
    __nv_bfloat162* ph = (__nv_bfloat162*)(ohi + e);
    __nv_bfloat162* pl = (__nv_bfloat162*)(olo + e);
    ph[0] = __nv_bfloat162(h0, h1); ph[1] = __nv_bfloat162(h2, h3);
    pl[0] = __nv_bfloat162(l0, l1); pl[1] = __nv_bfloat162(l2, l3);
}

// =================================================================
// KAN
// =================================================================
__device__ __forceinline__ void kan_bases(float x, float* out9)
{
    out9[0] = x / (1.0f + expf(-x));
    float b[11];
#pragma unroll
    for (int j = 0; j < 11; j++) {
        float gj  = (float)(j - 3) * 0.4f - 1.0f;
        float gj1 = (float)(j - 2) * 0.4f - 1.0f;
        b[j] = (x >= gj && x < gj1) ? 1.0f : 0.0f;
    }
#pragma unroll
    for (int p = 1; p <= 3; p++) {
        float inv = 1.0f / (0.4f * (float)p);
#pragma unroll
        for (int j = 0; j < 10; j++) {
            if (j < 11 - p) {
                float gj   = (float)(j - 3) * 0.4f - 1.0f;
                float gjp1 = (float)(j + p - 2) * 0.4f - 1.0f;
                b[j] = (x - gj) * inv * b[j] + (gjp1 - x) * inv * b[j + 1];
            }
        }
    }
#pragma unroll
    for (int j = 0; j < 8; j++) out9[1 + j] = b[j];
}

__global__ __launch_bounds__(256) void kan1_prep(
    const float* __restrict__ bw1, const float* __restrict__ sw1,
    const float* __restrict__ sc1, float* __restrict__ wAll)
{
    int idx = blockIdx.x * 256 + threadIdx.x;
    if (idx >= F1 * 9 * 32) return;
    int o = idx & 31;
    int t = idx >> 5;
    int c = t % 9;
    int i = t / 9;
    wAll[idx] = (c == 0) ? bw1[o * F1 + i]
                         : sw1[(o * F1 + i) * 8 + (c - 1)] * sc1[o * F1 + i];
}

__global__ __launch_bounds__(256) void kan1_kernel(
    const float* __restrict__ f, const float* __restrict__ wAll, float* __restrict__ f2)
{
    __shared__ float xs[32][16];
    __shared__ float augS[16 * 9][32];
    __shared__ float wS[16 * 9][32];

    int tid = threadIdx.x;
    int n0  = blockIdx.x * 32;
    int tx  = tid & 15;
    int ty  = tid >> 4;

    float a00 = 0.f, a01 = 0.f, a10 = 0.f, a11 = 0.f;

    for (int i0 = 0; i0 < F1; i0 += 16) {
        __syncthreads();
        if (tid < 128) {
            int r  = tid >> 2;
            int c4 = (tid & 3) * 4;
            *(float4*)&xs[r][c4] =
                *(const float4*)(f + (size_t)(n0 + r) * F1 + i0 + c4);
        }
        {
            const float4* src = (const float4*)(wAll + (size_t)i0 * 9 * 32);
            float4* dst = (float4*)&wS[0][0];
            for (int q = tid; q < (16 * 9 * 32) / 4; q += 256) dst[q] = src[q];
        }
        __syncthreads();
#pragma unroll
        for (int j = 0; j < 2; j++) {
            int p  = tid + j * 256;
            int r  = p & 31;
            int ci = p >> 5;
            float out9[9];
            kan_bases(xs[r][ci], out9);
#pragma unroll
            for (int c = 0; c < 9; c++) augS[ci * 9 + c][r] = out9[c];
        }
        __syncthreads();
#pragma unroll 4
        for (int kk = 0; kk < 16 * 9; kk++) {
            float x0 = augS[kk][ty], x1 = augS[kk][ty + 16];
            float w0 = wS[kk][tx],   w1 = wS[kk][tx + 16];
            a00 += x0 * w0; a01 += x0 * w1;
            a10 += x1 * w0; a11 += x1 * w1;
        }
    }

    f2[(size_t)(n0 + ty) * 32 + tx]           = a00;
    f2[(size_t)(n0 + ty) * 32 + tx + 16]      = a01;
    f2[(size_t)(n0 + ty + 16) * 32 + tx]      = a10;
    f2[(size_t)(n0 + ty + 16) * 32 + tx + 16] = a11;
}

__global__ __launch_bounds__(256) void kan2_kernel(
    const float* __restrict__ f2,
    const float* __restrict__ bw2, const float* __restrict__ sw2,
    const float* __restrict__ sc2, float* __restrict__ out)
{
    __shared__ float wS[10 * 32 * 9];
    for (int q = threadIdx.x; q < 10 * 32 * 9; q += 256) {
        int o = q / 288;
        int r = q % 288;
        int i = r / 9;
        int c = r % 9;
        wS[q] = (c == 0) ? bw2[o * 32 + i]
                         : sw2[(o * 32 + i) * 8 + (c - 1)] * sc2[o * 32 + i];
    }
    __syncthreads();

    int n = blockIdx.x * 256 + threadIdx.x;
    if (n >= NN) return;

    float xin[32];
#pragma unroll
    for (int q = 0; q < 8; q++)
        *(float4*)&xin[q * 4] = *(const float4*)(f2 + (size_t)n * 32 + q * 4);

    float acc[10];
#pragma unroll
    for (int o = 0; o < 10; o++) acc[o] = 0.f;

    for (int i = 0; i < 32; i++) {
        float out9[9];
        kan_bases(xin[i], out9);
#pragma unroll
        for (int o = 0; o < 10; o++) {
            const float* w = &wS[o * 288 + i * 9];
#pragma unroll
            for (int c = 0; c < 9; c++) acc[o] += out9[c] * w[c];
        }
    }
#pragma unroll
    for (int o = 0; o < 10; o++) out[(size_t)n * 10 + o] = acc[o];
}

// =================================================================
// launch
// =================================================================
extern "C" void kernel_launch(void* const* d_in, const int* in_sizes, int n_in,
                              void* d_out, int out_size)
{
    const float* x   = (const float*)d_in[0];
    const float* W1  = (const float*)d_in[3];
    const float* b1  = (const float*)d_in[4];
    const float* g1  = (const float*)d_in[5];
    const float* be1 = (const float*)d_in[6];
    const float* W2  = (const float*)d_in[7];
    const float* b2  = (const float*)d_in[8];
    const float* g2  = (const float*)d_in[9];
    const float* be2 = (const float*)d_in[10];
    const float* Wf  = (const float*)d_in[11];
    const float* bf  = (const float*)d_in[12];
    const float* bw1 = (const float*)d_in[13];
    const float* sw1 = (const float*)d_in[14];
    const float* sc1 = (const float*)d_in[15];
    const float* bw2 = (const float*)d_in[16];
    const float* sw2 = (const float*)d_in[17];
    const float* sc2 = (const float*)d_in[18];
    float* out = (float*)d_out;

    float *hfp, *fp, *f2p, *psp, *pqp, *scp, *shp, *wallp;
    __nv_bfloat16 *h1hi, *h1lo, *h2hi, *h2lo, *xhi, *xlo;
    __nv_bfloat16 *w1hi, *w1lo, *w2hi, *w2lo, *wfhi, *wflo;
    cudaGetSymbolAddress((void**)&hfp,   d_hf);
    cudaGetSymbolAddress((void**)&fp,    d_f);
    cudaGetSymbolAddress((void**)&f2p,   d_f2);
    cudaGetSymbolAddress((void**)&psp,   d_ps);
    cudaGetSymbolAddress((void**)&pqp,   d_pq);
    cudaGetSymbolAddress((void**)&scp,   d_scale);
    cudaGetSymbolAddress((void**)&shp,   d_shift);
    cudaGetSymbolAddress((void**)&wallp, d_wall);
    cudaGetSymbolAddress((void**)&h1hi,  d_h1hi);
    cudaGetSymbolAddress((void**)&h1lo,  d_h1lo);
    cudaGetSymbolAddress((void**)&h2hi,  d_h2hi);
    cudaGetSymbolAddress((void**)&h2lo,  d_h2lo);
    cudaGetSymbolAddress((void**)&xhi,   d_xhi);
    cudaGetSymbolAddress((void**)&xlo,   d_xlo);
    cudaGetSymbolAddress((void**)&w1hi,  d_w1hi);
    cudaGetSymbolAddress((void**)&w1lo,  d_w1lo);
    cudaGetSymbolAddress((void**)&w2hi,  d_w2hi);
    cudaGetSymbolAddress((void**)&w2lo,  d_w2lo);
    cudaGetSymbolAddress((void**)&wfhi,  d_wfhi);
    cudaGetSymbolAddress((void**)&wflo,  d_wflo);

    cudaFuncSetAttribute(mma_gemm<false, false>,
                         cudaFuncAttributeMaxDynamicSharedMemorySize, DYN_SMEM);
    cudaFuncSetAttribute(mma_gemm<true, true>,
                         cudaFuncAttributeMaxDynamicSharedMemorySize, DYN_SMEM);

    // ---- prep ----
    split_kernel<<<(BB * NN * FEAT / 4) / 256, 256>>>(x, xhi, xlo);
    tsplit_kernel<<<dim3(HD / 32, FEAT / 32, BB), 256>>>(W1, w1hi, w1lo, FEAT, HD);
    tsplit_kernel<<<dim3(HD / 32, HD / 32, BB),   256>>>(W2, w2hi, w2lo, HD, HD);
    tsplit_kernel<<<dim3(F1 / 32, CATK / 32, 1),  256>>>(Wf, wfhi, wflo, CATK, F1);
    kan1_prep<<<(F1 * 9 * 32 + 255) / 256, 256>>>(bw1, sw1, sc1, wallp);

    dim3 gemm12_grid(HD / 128, (NN + 127) / 128, BB);
    dim3 gemm3_grid(F1 / 128, (NN + 127) / 128, 1);
    dim3 bn_grid(NCHUNK, BB);

    // layer 1
    mma_gemm<false, false><<<gemm12_grid, 256, DYN_SMEM>>>(xhi, xlo, w1hi, w1lo, b1, hfp, NN, HD, FEAT);
    bn_partial<<<bn_grid, 256>>>(hfp, psp, pqp);
    bn_finalize<<<BB, 512>>>(psp, pqp, g1, be1, scp, shp);
    bn_apply_relu_split<<<(BB * NN * HD / 4) / 256, 256>>>(hfp, scp, shp, h1hi, h1lo);

    // layer 2
    mma_gemm<false, false><<<gemm12_grid, 256, DYN_SMEM>>>(h1hi, h1lo, w2hi, w2lo, b2, hfp, NN, HD, HD);
    bn_partial<<<bn_grid, 256>>>(hfp, psp, pqp);
    bn_finalize<<<BB, 512>>>(psp, pqp, g2, be2, scp, shp);
    bn_apply_relu_split<<<(BB * NN * HD / 4) / 256, 256>>>(hfp, scp, shp, h2hi, h2lo);

    // feature layer (concat folded into A-gather)
    mma_gemm<true, true><<<gemm3_grid, 256, DYN_SMEM>>>(h2hi, h2lo, wfhi, wflo, bf, fp, NN, F1, CATK);

    // KAN
    kan1_kernel<<<NN / 32, 256>>>(fp, wallp, f2p);
    kan2_kernel<<<(NN + 255) / 256, 256>>>(f2p, bw2, sw2, sc2, out);
}